// round 17
// baseline (speedup 1.0000x reference)
#include <cuda_runtime.h>
#include <cuda_fp16.h>
#include <cstdint>
#include <cstddef>

#define DEVI __device__ __forceinline__

// ---------------- problem dims ----------------
constexpr int DB = 2, DN = 384, DO = 4, DC = 128, DK = 64;
constexpr int SPLITS = 6;                  // split-K over source points n
constexpr int N_PER_SPLIT = DN / SPLITS;   // 64 source points per CTA
constexpr int NITER = N_PER_SPLIT;         // 64 stages, K=64 each (one n per stage)
constexpr int STAGES = 4;
constexpr int MTILES = 3;                  // 384 / 128
constexpr int GEMM_CTAS = SPLITS * MTILES * DB * DO;  // 144
constexpr int NGROUPS = DB * MTILES;       // 6 reduction groups (24 CTAs each)

constexpr int A_ROWF = 72;                 // A row stride in floats (64 + 8 pad)
constexpr int A_STAGE_F = 128 * A_ROWF;    // 9216 floats = 36864 B per stage
constexpr int X_STAGE_F = 128;             // one x row (512 B) per stage
constexpr int SMEM_FLOATS = STAGES * A_STAGE_F + STAGES * X_STAGE_F;
constexpr int SMEM_BYTES = SMEM_FLOATS * 4;   // 149504

// ---------------- static device scratch (no runtime allocation) ----------------
__device__ float g_Ypart[(size_t)SPLITS * DB * DN * DO * DC];  // [s][b][m][o][c] ~9.4 MB
__device__ int g_cnt[NGROUPS];                                 // zero-init; reset after use

// ---------------- PTX helpers ----------------
DEVI uint32_t smem_u32(const void* p) {
    uint32_t a;
    asm("{ .reg .u64 t; cvta.to.shared.u64 t, %1; cvt.u32.u64 %0, t; }" : "=r"(a) : "l"(p));
    return a;
}
DEVI void cp16(uint32_t dst, const void* src) {
    asm volatile("cp.async.cg.shared.global [%0], [%1], 16;" :: "r"(dst), "l"(src) : "memory");
}
DEVI void cp_commit() { asm volatile("cp.async.commit_group;" ::: "memory"); }
template <int N> DEVI void cp_wait() {
    asm volatile("cp.async.wait_group %0;" :: "n"(N) : "memory");
}
DEVI uint32_t pack_h2(float lo, float hi) {  // d = {lo half, hi half}
    uint32_t d;
    asm("cvt.rn.f16x2.f32 %0, %1, %2;" : "=r"(d) : "f"(hi), "f"(lo));
    return d;
}
DEVI uint32_t hmul2(uint32_t a, uint32_t b) {
    uint32_t d;
    asm("mul.rn.f16x2 %0, %1, %2;" : "=r"(d) : "r"(a), "r"(b));
    return d;
}
DEVI void mma_f16(float& c0, float& c1, float& c2, float& c3,
                  uint32_t a0, uint32_t a1, uint32_t a2, uint32_t a3,
                  uint32_t b0, uint32_t b1) {
    asm volatile(
        "mma.sync.aligned.m16n8k16.row.col.f32.f16.f16.f32 "
        "{%0,%1,%2,%3}, {%4,%5,%6,%7}, {%8,%9}, {%0,%1,%2,%3};"
        : "+f"(c0), "+f"(c1), "+f"(c2), "+f"(c3)
        : "r"(a0), "r"(a1), "r"(a2), "r"(a3), "r"(b0), "r"(b1));
}

// ---------------- fused GEMM + last-CTA reduction ----------------
// CTA (256 thr, warp grid 2(M) x 4(N), warp tile 64x32):
//   Ypart[s][b][m0:m0+128][o][:] = KB_tile[128, 4096] @ B^T, with
//   B[c][n*64+k] = half(x[b,n,o,c]) * half(W_spatial[k,c]) generated in registers.
// The 24th CTA to finish each (b, mt) group performs rot + split-K reduce + bias.
__global__ void __launch_bounds__(256, 1) sepconv_gemm(const float* __restrict__ KB,
                                                       const float* __restrict__ x,
                                                       const float* __restrict__ Ws,
                                                       const float* __restrict__ fkb,
                                                       const float* __restrict__ Wr,
                                                       const float* __restrict__ bias,
                                                       float* __restrict__ out) {
    extern __shared__ float sm[];  // [STAGES][A fp32 128x72] then [STAGES][x 128]

    const int tid = threadIdx.x;
    const int w = tid >> 5, lid = tid & 31;
    const int gid = lid >> 2, tig = lid & 3;
    const int wm = w >> 2, wn = w & 3;   // warp grid 2 (M) x 4 (N)

    const int cta = blockIdx.x;          // 0..143
    const int s  = cta % SPLITS;
    const int mt = (cta / SPLITS) % MTILES;
    const int bo = cta / (SPLITS * MTILES);
    const int b = bo >> 2, o = bo & 3;
    const int m0 = mt * 128;
    const int n0 = s * N_PER_SPLIT;

    // ---- loop-invariant W fragment registers ----
    uint32_t Wreg[4][4][2];
    #pragma unroll
    for (int ni = 0; ni < 4; ni++) {
        const int c = wn * 32 + ni * 8 + gid;
        #pragma unroll
        for (int kk = 0; kk < 4; kk++)
            #pragma unroll
            for (int j = 0; j < 2; j++) {
                const int k = kk * 16 + 2 * tig + 8 * j;
                Wreg[ni][kk][j] = pack_h2(Ws[k * DC + c], Ws[(k + 1) * DC + c]);
            }
    }

    // ---- A loaders: 2 threads per row, 32 floats each ----
    const int lrow = tid >> 1, lsub = tid & 1;
    const float* aSrc = KB + (size_t)b * ((size_t)DN * DN * DO * DK)
                           + (size_t)(m0 + lrow) * (DN * DO * DK)
                           + (size_t)n0 * (DO * DK) + (size_t)o * DK + lsub * 32;
    const float* xSrc = x + ((size_t)(b * DN + n0) * DO + o) * DC;  // +it*512 per stage
    const uint32_t smem0 = smem_u32(sm);
    const uint32_t aDst0 = smem0 + (uint32_t)lrow * (A_ROWF * 4) + (uint32_t)lsub * 128;
    const uint32_t xBase = smem0 + STAGES * A_STAGE_F * 4;

    auto load_stage = [&](int st) {
        const uint32_t so = (uint32_t)(st % STAGES) * (A_STAGE_F * 4);
        const float* src = aSrc + (size_t)st * (DO * DK);
        const uint32_t d = aDst0 + so;
        #pragma unroll
        for (int j = 0; j < 8; j++) cp16(d + j * 16, src + j * 4);
        if (tid < 32)
            cp16(xBase + (uint32_t)(st % STAGES) * 512 + (uint32_t)tid * 16,
                 xSrc + (size_t)st * (DO * DC) + tid * 4);
    };

    float acc[4][4][4];
    #pragma unroll
    for (int mi = 0; mi < 4; mi++)
        #pragma unroll
        for (int ni = 0; ni < 4; ni++)
            #pragma unroll
            for (int r = 0; r < 4; r++) acc[mi][ni][r] = 0.f;

    // ---- prologue ----
    #pragma unroll
    for (int st = 0; st < STAGES - 1; st++) { load_stage(st); cp_commit(); }

    // ---- mainloop: one source point n (K=64) per iteration ----
    for (int it = 0; it < NITER; it++) {
        cp_wait<STAGES - 2>();   // stage `it` resident
        __syncthreads();
        if (it + STAGES - 1 < NITER) load_stage(it + STAGES - 1);
        cp_commit();

        const float* As = sm + (it % STAGES) * A_STAGE_F;
        const float* xs = sm + STAGES * A_STAGE_F + (it % STAGES) * X_STAGE_F;

        uint32_t xh2[4];
        #pragma unroll
        for (int ni = 0; ni < 4; ni++) {
            const float xv = xs[wn * 32 + ni * 8 + gid];
            xh2[ni] = pack_h2(xv, xv);
        }

        #pragma unroll
        for (int kk = 0; kk < 4; kk++) {   // K=16 chunks
            uint32_t a[4][4];
            #pragma unroll
            for (int mi = 0; mi < 4; mi++) {
                const float* ap = As + (wm * 64 + mi * 16 + gid) * A_ROWF + kk * 16 + 2 * tig;
                const float2 v00 = *(const float2*)(ap);
                const float2 v10 = *(const float2*)(ap + 8 * A_ROWF);
                const float2 v01 = *(const float2*)(ap + 8);
                const float2 v11 = *(const float2*)(ap + 8 * A_ROWF + 8);
                a[mi][0] = pack_h2(v00.x, v00.y);
                a[mi][1] = pack_h2(v10.x, v10.y);
                a[mi][2] = pack_h2(v01.x, v01.y);
                a[mi][3] = pack_h2(v11.x, v11.y);
            }
            uint32_t bf[4][2];
            #pragma unroll
            for (int ni = 0; ni < 4; ni++) {
                bf[ni][0] = hmul2(xh2[ni], Wreg[ni][kk][0]);
                bf[ni][1] = hmul2(xh2[ni], Wreg[ni][kk][1]);
            }
            #pragma unroll
            for (int mi = 0; mi < 4; mi++)
                #pragma unroll
                for (int ni = 0; ni < 4; ni++)
                    mma_f16(acc[mi][ni][0], acc[mi][ni][1], acc[mi][ni][2], acc[mi][ni][3],
                            a[mi][0], a[mi][1], a[mi][2], a[mi][3],
                            bf[ni][0], bf[ni][1]);
        }
    }

    // ---- epilogue: write partials ----
    #pragma unroll
    for (int mi = 0; mi < 4; mi++) {
        const int row = m0 + wm * 64 + mi * 16 + gid;
        float* y0 = g_Ypart + ((((size_t)s * DB + b) * DN + row) * DO + o) * DC;
        float* y1 = g_Ypart + ((((size_t)s * DB + b) * DN + row + 8) * DO + o) * DC;
        #pragma unroll
        for (int ni = 0; ni < 4; ni++) {
            const int col = wn * 32 + ni * 8 + 2 * tig;
            *(float2*)(y0 + col) = make_float2(acc[mi][ni][0], acc[mi][ni][1]);
            *(float2*)(y1 + col) = make_float2(acc[mi][ni][2], acc[mi][ni][3]);
        }
    }

    // ---- last-CTA-done reduction for this (b, mt) group ----
    __threadfence();
    __syncthreads();
    __shared__ int isLast;
    const int grp = b * MTILES + mt;
    if (tid == 0) {
        const int old = atomicAdd(&g_cnt[grp], 1);
        isLast = (old == SPLITS * DO - 1);
    }
    __syncthreads();
    if (!isLast) return;
    if (tid == 0) g_cnt[grp] = 0;          // reset for next graph replay
    __threadfence();                        // acquire: see all partials

    // -- rot[p][o][c] into smem (reuse pipeline smem) --
    float* fks = sm;                        // 16*64 floats
    float* rot_s = sm + 16 * DK;            // 16*128 floats
    for (int i = tid; i < 16 * DK; i += 256) fks[i] = fkb[i];
    __syncthreads();
    {
        const int c = tid & 127;
        const int ph = tid >> 7;            // 0..1 -> po groups of 8
        float racc[8];
        #pragma unroll
        for (int q = 0; q < 8; q++) racc[q] = 0.f;
        #pragma unroll 8
        for (int k = 0; k < DK; k++) {
            const float wv = Wr[k * DC + c];
            #pragma unroll
            for (int q = 0; q < 8; q++)
                racc[q] += fks[(ph * 8 + q) * DK + k] * wv;
        }
        __syncthreads();                    // fks reads done before rot_s overwrite-safe zone
        #pragma unroll
        for (int q = 0; q < 8; q++) rot_s[(ph * 8 + q) * DC + c] = racc[q];
    }
    __syncthreads();

    // -- split-K reduce + fiber mix + bias for rows [m0, m0+128) of batch b --
    const int c2 = (tid & 63) * 2;          // float2 column
    const int mstep = tid >> 6;             // 0..3
    const float2 bi = *(const float2*)(bias + c2);
    for (int ml = mstep; ml < 128; ml += 4) {
        const int m = m0 + ml;
        float2 y[DO];
        #pragma unroll
        for (int o2 = 0; o2 < DO; o2++) y[o2] = make_float2(0.f, 0.f);
        #pragma unroll
        for (int s2 = 0; s2 < SPLITS; s2++) {
            const float* p = g_Ypart + (((size_t)s2 * DB + b) * DN + m) * DO * DC + c2;
            #pragma unroll
            for (int o2 = 0; o2 < DO; o2++) {
                const float2 v = *(const float2*)(p + o2 * DC);
                y[o2].x += v.x; y[o2].y += v.y;
            }
        }
        #pragma unroll
        for (int p2 = 0; p2 < DO; p2++) {
            float ax = bi.x, ay = bi.y;
            #pragma unroll
            for (int o2 = 0; o2 < DO; o2++) {
                const float2 r = *(const float2*)(rot_s + (p2 * 4 + o2) * DC + c2);
                ax += y[o2].x * r.x;
                ay += y[o2].y * r.y;
            }
            *(float2*)(out + (((size_t)b * DN + m) * DO + p2) * DC + c2) = make_float2(ax, ay);
        }
    }
}

// ---------------- launcher ----------------
extern "C" void kernel_launch(void* const* d_in, const int* in_sizes, int n_in,
                              void* d_out, int out_size) {
    (void)in_sizes; (void)n_in; (void)out_size;
    const float* x    = (const float*)d_in[0];
    const float* KB   = (const float*)d_in[1];
    const float* fkb  = (const float*)d_in[2];
    const float* Ws   = (const float*)d_in[3];
    const float* Wr   = (const float*)d_in[4];
    const float* bias = (const float*)d_in[5];
    float* out = (float*)d_out;

    static bool attr_done = false;
    if (!attr_done) {
        cudaFuncSetAttribute(sepconv_gemm, cudaFuncAttributeMaxDynamicSharedMemorySize,
                             SMEM_BYTES);
        attr_done = true;
    }

    sepconv_gemm<<<GEMM_CTAS, 256, SMEM_BYTES>>>(KB, x, Ws, fkb, Wr, bias, out);
}